// round 4
// baseline (speedup 1.0000x reference)
#include <cuda_runtime.h>
#include <cstddef>

#define D_DIM   64
#define N_USERS 4096
#define N_ITEMS 16384
#define L_U     50
#define L_I     20
#define OUT_W   (D_DIM + 2)   // 66
#define N_ROWS  (N_USERS + N_ITEMS)

// One warp per output row. LDG.128 fetches 2 feature rows per warp-load:
//   lanes 0-15  (half=0): feature 2p,   columns sub*4 .. sub*4+3
//   lanes 16-31 (half=1): feature 2p+1, columns sub*4 .. sub*4+3
// where sub = lane & 15. Even/odd-feature partials merged via shfl_xor(16).
template <int L, bool IS_USER>
__device__ __forceinline__
void do_row(const float* __restrict__ emb,
            const float* __restrict__ w,
            float                     bias,
            const float* __restrict__ h1,
            const int*   __restrict__ my_idx,
            float*       __restrict__ orow,
            int lane)
{
    static_assert(L % 2 == 0, "L must be even");
    constexpr int NP = L / 2;          // pair-loads per row
    const int half = lane >> 4;        // 0 or 1
    const int sub  = lane & 15;        // column group

    // Preload indices into registers.
    int idx_lo = (L >= 32 || lane < L) ? my_idx[lane] : 0;
    int idx_hi = 0;
    if (L > 32) idx_hi = (lane + 32 < L) ? my_idx[lane + 32] : 0;

    // w-gather partials
    float wsum = 0.f;
    if (L >= 32 || lane < L) wsum += __ldg(&w[idx_lo]);
    if (L > 32 && lane + 32 < L) wsum += __ldg(&w[idx_hi]);

    float a0 = 0.f, a1 = 0.f, a2 = 0.f, a3 = 0.f;   // column sums
    float q0 = 0.f, q1 = 0.f, q2 = 0.f, q3 = 0.f;   // column sums of squares

    constexpr int B = 5;  // pair-loads staged per batch (20 f32 data regs)
    #pragma unroll
    for (int p0 = 0; p0 < NP; p0 += B) {
        float4 g[B];
        #pragma unroll
        for (int k = 0; k < B; ++k) {
            const int p = p0 + k;
            if (p < NP) {
                // feature index f = 2p + half; source lane = f mod 32,
                // register = idx_lo for p<16 else idx_hi (2p,2p+1 same side).
                int src = (2 * p < 32) ? idx_lo : idx_hi;
                int r   = __shfl_sync(0xffffffffu, src, (2 * p + half) & 31);
                g[k] = *reinterpret_cast<const float4*>(
                           emb + (size_t)r * D_DIM + sub * 4);
            } else {
                g[k].x = g[k].y = g[k].z = g[k].w = 0.f;
            }
        }
        #pragma unroll
        for (int k = 0; k < B; ++k) {
            a0 += g[k].x; q0 += g[k].x * g[k].x;
            a1 += g[k].y; q1 += g[k].y * g[k].y;
            a2 += g[k].z; q2 += g[k].z * g[k].z;
            a3 += g[k].w; q3 += g[k].w * g[k].w;
        }
    }

    // Merge even-feature (half=0) and odd-feature (half=1) partials.
    a0 += __shfl_xor_sync(0xffffffffu, a0, 16);
    a1 += __shfl_xor_sync(0xffffffffu, a1, 16);
    a2 += __shfl_xor_sync(0xffffffffu, a2, 16);
    a3 += __shfl_xor_sync(0xffffffffu, a3, 16);
    q0 += __shfl_xor_sync(0xffffffffu, q0, 16);
    q1 += __shfl_xor_sync(0xffffffffu, q1, 16);
    q2 += __shfl_xor_sync(0xffffffffu, q2, 16);
    q3 += __shfl_xor_sync(0xffffffffu, q3, 16);

    // Lane (half,sub) owns columns sub*4 + 2*half, +1 for store & scalar.
    const int col = sub * 4 + 2 * half;
    float sc0 = (half == 0) ? a0 : a2;
    float sc1 = (half == 0) ? a1 : a3;
    float qc0 = (half == 0) ? q0 : q2;
    float qc1 = (half == 0) ? q1 : q3;

    float2 h = *reinterpret_cast<const float2*>(h1 + col);
    float bi0 = 0.5f * (sc0 * sc0 - qc0);
    float bi1 = 0.5f * (sc1 * sc1 - qc1);
    float part = bi0 * h.x + bi1 * h.y + wsum;

    #pragma unroll
    for (int o = 16; o > 0; o >>= 1)
        part += __shfl_xor_sync(0xffffffffu, part, o);

    float2 sv; sv.x = sc0; sv.y = sc1;
    *reinterpret_cast<float2*>(orow + col) = sv;   // 8B aligned (col even, stride 66 even)

    if (lane == 0) {
        if (IS_USER) {
            orow[D_DIM]     = part + bias;
            orow[D_DIM + 1] = 1.0f;
        } else {
            orow[D_DIM]     = 1.0f;
            orow[D_DIM + 1] = part;
        }
    }
}

__global__ __launch_bounds__(256)
void fm_fused_kernel(const float* __restrict__ uemb,
                     const float* __restrict__ iemb,
                     const float* __restrict__ uw,
                     const float* __restrict__ iw,
                     const float* __restrict__ gbias,
                     const float* __restrict__ h1,
                     const float* __restrict__ h2,
                     const int*   __restrict__ uidx,
                     const int*   __restrict__ iidx,
                     float*       __restrict__ out)
{
    const int lane = threadIdx.x & 31;
    const int gw   = (blockIdx.x * blockDim.x + threadIdx.x) >> 5;

    if (blockIdx.x == 0 && threadIdx.x < D_DIM) {
        out[(size_t)N_ROWS * OUT_W + threadIdx.x] = h2[threadIdx.x];
    }

    if (gw < N_USERS) {
        do_row<L_U, true>(uemb, uw, gbias[0], h1,
                          uidx + (size_t)gw * L_U,
                          out + (size_t)gw * OUT_W, lane);
    } else if (gw < N_ROWS) {
        const int row = gw - N_USERS;
        do_row<L_I, false>(iemb, iw, 0.f, h1,
                           iidx + (size_t)row * L_I,
                           out + (size_t)(N_USERS + row) * OUT_W, lane);
    }
}

extern "C" void kernel_launch(void* const* d_in, const int* in_sizes, int n_in,
                              void* d_out, int out_size)
{
    const float* uemb  = (const float*)d_in[0];
    const float* iemb  = (const float*)d_in[1];
    const float* uw    = (const float*)d_in[2];
    const float* iw    = (const float*)d_in[3];
    const float* gbias = (const float*)d_in[4];
    const float* h1    = (const float*)d_in[5];
    const float* h2    = (const float*)d_in[6];
    const int*   uidx  = (const int*)d_in[7];
    const int*   iidx  = (const int*)d_in[8];

    float* out = (float*)d_out;

    const int threads = 256;
    const int warps_per_block = threads / 32;
    const int blocks = (N_ROWS + warps_per_block - 1) / warps_per_block;

    fm_fused_kernel<<<blocks, threads>>>(uemb, iemb, uw, iw, gbias, h1, h2,
                                         uidx, iidx, out);
}

// round 5
// speedup vs baseline: 1.0020x; 1.0020x over previous
#include <cuda_runtime.h>
#include <cstddef>
#include <cstdint>

#define D_DIM   64
#define N_USERS 4096
#define N_ITEMS 16384
#define L_U     50
#define L_I     20
#define OUT_W   (D_DIM + 2)   // 66
#define N_ROWS  (N_USERS + N_ITEMS)
#define CHUNK   10            // embedding rows per cp.async group
#define WPB     8             // warps per block

// cp.async double-buffered gather pipeline.
// Per warp: stage CHUNK rows (256B each) into smem via cp.async.cg (no dest
// regs -> MLP cannot be collapsed by ptxas), overlap with accumulation of the
// previous chunk. Lane l owns output columns 2l, 2l+1.
template <int L, bool IS_USER>
__device__ __forceinline__
void do_row(const float* __restrict__ emb,
            const float* __restrict__ w,
            float                     bias,
            const float* __restrict__ h1,
            const int*   __restrict__ my_idx,
            float*       __restrict__ orow,
            int lane,
            float*       __restrict__ sbuf)   // [2][CHUNK][64] floats, this warp's
{
    static_assert(L % CHUNK == 0, "L must be a multiple of CHUNK");
    constexpr int NC = L / CHUNK;
    const int half = lane >> 4;        // 0: even rows of chunk, 1: odd rows
    const int sub  = lane & 15;        // 16B slot within a 256B row

    // Indices live in registers; broadcast by shuffle.
    int idx_lo = (L >= 32 || lane < L) ? my_idx[lane] : 0;
    int idx_hi = 0;
    if (L > 32) idx_hi = (lane + 32 < L) ? my_idx[lane + 32] : 0;

    float wsum = 0.f;
    if (L >= 32 || lane < L) wsum += __ldg(&w[idx_lo]);
    if (L > 32 && lane + 32 < L) wsum += __ldg(&w[idx_hi]);

    const uint32_t sb = (uint32_t)__cvta_generic_to_shared(sbuf);

    // Stage chunk c into buffer buf. One warp-instruction covers 2 rows:
    // lanes 0-15 row 2t, lanes 16-31 row 2t+1 (within the chunk).
    auto prefetch = [&](int c, int buf) {
        #pragma unroll
        for (int t = 0; t < CHUNK / 2; ++t) {
            const int f = c * CHUNK + 2 * t + half;           // feature slot
            int src = (c * CHUNK + 2 * t < 32) ? idx_lo : idx_hi;
            int r   = __shfl_sync(0xffffffffu, src, f & 31);
            uint32_t dst = sb + (uint32_t)(buf * CHUNK + 2 * t + half) * 256u
                              + (uint32_t)sub * 16u;
            const float* sp = emb + (size_t)r * D_DIM + sub * 4;
            asm volatile("cp.async.cg.shared.global [%0], [%1], 16;\n"
                         :: "r"(dst), "l"(sp));
        }
        asm volatile("cp.async.commit_group;\n" ::: "memory");
    };

    float sx = 0.f, sy = 0.f, qx = 0.f, qy = 0.f;

    auto consume = [&](int buf) {
        #pragma unroll
        for (int j = 0; j < CHUNK; ++j) {
            float2 v = *reinterpret_cast<const float2*>(
                sbuf + (buf * CHUNK + j) * D_DIM + lane * 2);
            sx += v.x; sy += v.y;
            qx += v.x * v.x; qy += v.y * v.y;
        }
    };

    prefetch(0, 0);
    #pragma unroll
    for (int c = 0; c < NC; ++c) {
        if (c + 1 < NC) {
            prefetch(c + 1, (c + 1) & 1);
            asm volatile("cp.async.wait_group 1;\n" ::: "memory");
        } else {
            asm volatile("cp.async.wait_group 0;\n" ::: "memory");
        }
        __syncwarp();          // make staged bytes visible across lanes
        consume(c & 1);
        __syncwarp();          // reads done before buffer is re-staged
    }

    float2 h = *reinterpret_cast<const float2*>(h1 + 2 * lane);
    float part = 0.5f * (sx * sx - qx) * h.x
               + 0.5f * (sy * sy - qy) * h.y + wsum;

    #pragma unroll
    for (int o = 16; o > 0; o >>= 1)
        part += __shfl_xor_sync(0xffffffffu, part, o);

    float2 sv; sv.x = sx; sv.y = sy;
    *reinterpret_cast<float2*>(orow + 2 * lane) = sv;   // stride 66 even -> 8B aligned

    if (lane == 0) {
        if (IS_USER) {
            orow[D_DIM]     = part + bias;
            orow[D_DIM + 1] = 1.0f;
        } else {
            orow[D_DIM]     = 1.0f;
            orow[D_DIM + 1] = part;
        }
    }
}

__global__ __launch_bounds__(WPB * 32)
void fm_fused_kernel(const float* __restrict__ uemb,
                     const float* __restrict__ iemb,
                     const float* __restrict__ uw,
                     const float* __restrict__ iw,
                     const float* __restrict__ gbias,
                     const float* __restrict__ h1,
                     const float* __restrict__ h2,
                     const int*   __restrict__ uidx,
                     const int*   __restrict__ iidx,
                     float*       __restrict__ out)
{
    __shared__ float sbuf[WPB][2 * CHUNK * D_DIM];   // 40 KB

    const int lane = threadIdx.x & 31;
    const int wib  = threadIdx.x >> 5;                     // warp in block
    const int gw   = blockIdx.x * WPB + wib;               // global warp id

    if (blockIdx.x == 0 && threadIdx.x < D_DIM) {
        out[(size_t)N_ROWS * OUT_W + threadIdx.x] = h2[threadIdx.x];
    }

    if (gw < N_USERS) {
        do_row<L_U, true>(uemb, uw, gbias[0], h1,
                          uidx + (size_t)gw * L_U,
                          out + (size_t)gw * OUT_W, lane, sbuf[wib]);
    } else if (gw < N_ROWS) {
        const int row = gw - N_USERS;
        do_row<L_I, false>(iemb, iw, 0.f, h1,
                           iidx + (size_t)row * L_I,
                           out + (size_t)(N_USERS + row) * OUT_W, lane, sbuf[wib]);
    }
}

extern "C" void kernel_launch(void* const* d_in, const int* in_sizes, int n_in,
                              void* d_out, int out_size)
{
    const float* uemb  = (const float*)d_in[0];
    const float* iemb  = (const float*)d_in[1];
    const float* uw    = (const float*)d_in[2];
    const float* iw    = (const float*)d_in[3];
    const float* gbias = (const float*)d_in[4];
    const float* h1    = (const float*)d_in[5];
    const float* h2    = (const float*)d_in[6];
    const int*   uidx  = (const int*)d_in[7];
    const int*   iidx  = (const int*)d_in[8];

    float* out = (float*)d_out;

    const int blocks = (N_ROWS + WPB - 1) / WPB;   // 2560
    fm_fused_kernel<<<blocks, WPB * 32>>>(uemb, iemb, uw, iw, gbias, h1, h2,
                                          uidx, iidx, out);
}

// round 6
// speedup vs baseline: 1.0158x; 1.0139x over previous
#include <cuda_runtime.h>
#include <cstddef>

#define D_DIM   64
#define N_USERS 4096
#define N_ITEMS 16384
#define L_U     50
#define L_I     20
#define L_UH    (L_U / 2)     // 25 per half-warp
#define OUT_W   (D_DIM + 2)   // 66
#define N_ROWS  (N_USERS + N_ITEMS)
#define WPB     8

#define UROWS_PER_BLOCK (WPB / 2)                       // 4 user rows / block
#define N_UBLOCKS (N_USERS / UROWS_PER_BLOCK)           // 1024
#define N_IBLOCKS (N_ITEMS / WPB)                       // 2048

// ---------- item path: one warp per row, L=20 gathers ----------
__device__ __forceinline__
void item_row(const float* __restrict__ emb,
              const float* __restrict__ w,
              const float* __restrict__ h1,
              const int*   __restrict__ my_idx,
              float*       __restrict__ orow,
              int lane)
{
    int idx_r = (lane < L_I) ? my_idx[lane] : 0;
    float wsum = (lane < L_I) ? __ldg(&w[idx_r]) : 0.f;

    float sx = 0.f, sy = 0.f, qx = 0.f, qy = 0.f;
    #pragma unroll
    for (int j = 0; j < L_I; ++j) {
        int r = __shfl_sync(0xffffffffu, idx_r, j);
        float2 g = *reinterpret_cast<const float2*>(emb + (size_t)r * D_DIM + 2 * lane);
        sx += g.x; sy += g.y;
        qx += g.x * g.x; qy += g.y * g.y;
    }

    float2 h = *reinterpret_cast<const float2*>(h1 + 2 * lane);
    float part = 0.5f * (sx * sx - qx) * h.x
               + 0.5f * (sy * sy - qy) * h.y + wsum;
    #pragma unroll
    for (int o = 16; o > 0; o >>= 1)
        part += __shfl_xor_sync(0xffffffffu, part, o);

    float2 sv; sv.x = sx; sv.y = sy;
    *reinterpret_cast<float2*>(orow + 2 * lane) = sv;
    if (lane == 0) {
        orow[D_DIM]     = 1.0f;
        orow[D_DIM + 1] = part;
    }
}

__global__ __launch_bounds__(WPB * 32)
void fm_kernel(const float* __restrict__ uemb,
               const float* __restrict__ iemb,
               const float* __restrict__ uw,
               const float* __restrict__ iw,
               const float* __restrict__ gbias,
               const float* __restrict__ h1,
               const float* __restrict__ h2,
               const int*   __restrict__ uidx,
               const int*   __restrict__ iidx,
               float*       __restrict__ out)
{
    const int lane = threadIdx.x & 31;
    const int wib  = threadIdx.x >> 5;

    if (blockIdx.x == 0 && threadIdx.x < D_DIM)
        out[(size_t)N_ROWS * OUT_W + threadIdx.x] = h2[threadIdx.x];

    if (blockIdx.x < N_UBLOCKS) {
        // ---------- user path: 2 warps per row, 25 gathers each ----------
        // smem: per warp, per lane: sx, sy, qx, qy, wsum
        __shared__ float comb[WPB][32][5];

        const int rloc = wib >> 1;           // row within block (0..3)
        const int half = wib & 1;            // which 25 features
        const int row  = blockIdx.x * UROWS_PER_BLOCK + rloc;
        const int* my_idx = uidx + (size_t)row * L_U + half * L_UH;

        int idx_r = (lane < L_UH) ? my_idx[lane] : 0;
        float wsum = (lane < L_UH) ? __ldg(&uw[idx_r]) : 0.f;

        float sx = 0.f, sy = 0.f, qx = 0.f, qy = 0.f;
        #pragma unroll
        for (int j = 0; j < L_UH; ++j) {
            int r = __shfl_sync(0xffffffffu, idx_r, j);
            float2 g = *reinterpret_cast<const float2*>(uemb + (size_t)r * D_DIM + 2 * lane);
            sx += g.x; sy += g.y;
            qx += g.x * g.x; qy += g.y * g.y;
        }

        comb[wib][lane][0] = sx;
        comb[wib][lane][1] = sy;
        comb[wib][lane][2] = qx;
        comb[wib][lane][3] = qy;
        comb[wib][lane][4] = wsum;
        __syncthreads();

        if (half == 0) {
            const int pw = wib | 1;          // partner warp
            sx   += comb[pw][lane][0];
            sy   += comb[pw][lane][1];
            qx   += comb[pw][lane][2];
            qy   += comb[pw][lane][3];
            wsum += comb[pw][lane][4];

            float2 h = *reinterpret_cast<const float2*>(h1 + 2 * lane);
            float part = 0.5f * (sx * sx - qx) * h.x
                       + 0.5f * (sy * sy - qy) * h.y + wsum;
            #pragma unroll
            for (int o = 16; o > 0; o >>= 1)
                part += __shfl_xor_sync(0xffffffffu, part, o);

            float* orow = out + (size_t)row * OUT_W;
            float2 sv; sv.x = sx; sv.y = sy;
            *reinterpret_cast<float2*>(orow + 2 * lane) = sv;
            if (lane == 0) {
                orow[D_DIM]     = part + gbias[0];
                orow[D_DIM + 1] = 1.0f;
            }
        }
    } else {
        // ---------- item blocks: warp-per-row ----------
        const int row = (blockIdx.x - N_UBLOCKS) * WPB + wib;
        if (row < N_ITEMS) {
            item_row(iemb, iw, h1,
                     iidx + (size_t)row * L_I,
                     out + (size_t)(N_USERS + row) * OUT_W, lane);
        }
    }
}

extern "C" void kernel_launch(void* const* d_in, const int* in_sizes, int n_in,
                              void* d_out, int out_size)
{
    const float* uemb  = (const float*)d_in[0];
    const float* iemb  = (const float*)d_in[1];
    const float* uw    = (const float*)d_in[2];
    const float* iw    = (const float*)d_in[3];
    const float* gbias = (const float*)d_in[4];
    const float* h1    = (const float*)d_in[5];
    const float* h2    = (const float*)d_in[6];
    const int*   uidx  = (const int*)d_in[7];
    const int*   iidx  = (const int*)d_in[8];

    float* out = (float*)d_out;

    const int blocks = N_UBLOCKS + N_IBLOCKS;   // 3072
    fm_kernel<<<blocks, WPB * 32>>>(uemb, iemb, uw, iw, gbias, h1, h2,
                                    uidx, iidx, out);
}